// round 6
// baseline (speedup 1.0000x reference)
#include <cuda_runtime.h>
#include <cuda_bf16.h>
#include <math.h>
#include <stdint.h>

constexpr int MT = 32768;
constexpr int D  = 256;

// ---------------- smem layout (bytes) ----------------
constexpr int OFF_SA   = 0;            // float[256]  BN scale a[k]
constexpr int OFF_SC   = 1024;         // float[256]  BN shift c[k]
constexpr int OFF_BIAS = 2048;         // float[128]  folded bias (this n-half)
constexpr int OFF_SUM  = 2560;         // float[128]
constexpr int OFF_SQ   = 3072;         // float[128]
constexpr int OFF_B    = 4096;         // B hi plane: 256 rows x 272B
constexpr int BSTR     = 272;          // 128 bf16 + 8 pad
constexpr int B_PLANE  = 256 * BSTR;   // 69632
constexpr int OFF_A    = OFF_B + 2 * B_PLANE;   // 143360
constexpr int ASTR     = 144;          // 64 bf16 + 8 pad
constexpr int A_PLANE  = 128 * ASTR;   // 18432
constexpr int A_STG    = 2 * A_PLANE;  // 36864 (hi+lo)
constexpr int SMEM_TOTAL = OFF_A + 2 * A_STG;   // 217088

// ---------------- device scratch ----------------
__device__ __nv_bfloat16 g_actHi[2][(size_t)MT * D];
__device__ __nv_bfloat16 g_actLo[2][(size_t)MT * D];
__device__ float g_sum[3 * D];
__device__ float g_sq[3 * D];

// ---------------- helpers ----------------
__device__ __forceinline__ uint32_t smem_u32(const void* p) {
    return (uint32_t)__cvta_generic_to_shared(p);
}
__device__ __forceinline__ void cp16(uint32_t sdst, const void* gsrc) {
    asm volatile("cp.async.cg.shared.global [%0], [%1], 16;\n" :: "r"(sdst), "l"(gsrc));
}
#define CP_COMMIT asm volatile("cp.async.commit_group;\n" ::: "memory")

__device__ __forceinline__ float gelu_exact(float x) {
    return 0.5f * x * (1.0f + erff(x * 0.70710678118654752f));
}
__device__ __forceinline__ void split_bf16(float x, __nv_bfloat16& hi, __nv_bfloat16& lo) {
    hi = __float2bfloat16(x);
    lo = __float2bfloat16(x - __bfloat162float(hi));
}

#define LDSM4(r, addr) \
    asm volatile("ldmatrix.sync.aligned.m8n8.x4.shared.b16 {%0,%1,%2,%3}, [%4];" \
                 : "=r"((r)[0]), "=r"((r)[1]), "=r"((r)[2]), "=r"((r)[3]) : "r"(addr))
#define LDSM4T(r, addr) \
    asm volatile("ldmatrix.sync.aligned.m8n8.x4.trans.shared.b16 {%0,%1,%2,%3}, [%4];" \
                 : "=r"((r)[0]), "=r"((r)[1]), "=r"((r)[2]), "=r"((r)[3]) : "r"(addr))
#define MMA(acc, a, b0_, b1_) \
    asm volatile("mma.sync.aligned.m16n8k16.row.col.f32.bf16.bf16.f32 " \
                 "{%0,%1,%2,%3}, {%4,%5,%6,%7}, {%8,%9}, {%0,%1,%2,%3};" \
                 : "+f"((acc)[0]), "+f"((acc)[1]), "+f"((acc)[2]), "+f"((acc)[3]) \
                 : "r"((a)[0]), "r"((a)[1]), "r"((a)[2]), "r"((a)[3]), \
                   "r"(b0_), "r"(b1_))

// ================= prep0: zero stats + gather + bf16 split of table rows =================
__global__ __launch_bounds__(256)
void prep0_kernel(const int* __restrict__ ids, const float* __restrict__ table) {
    const int tid = threadIdx.x, blk = blockIdx.x;
    if (blk == 0) {
        for (int i = tid; i < 3 * D; i += 256) { g_sum[i] = 0.f; g_sq[i] = 0.f; }
    }
    const int col2 = (tid & 127) * 2;
    const int rsub = tid >> 7;
    uint32_t* dstH = (uint32_t*)g_actHi[0];
    uint32_t* dstL = (uint32_t*)g_actLo[0];
#pragma unroll 4
    for (int i = 0; i < 64; i++) {
        int row = blk * 128 + rsub + i * 2;
        int id  = __ldg(ids + row);
        float2 x = *(const float2*)(table + (size_t)id * D + col2);
        union { __nv_bfloat16 h[2]; uint32_t u; } ph, pl;
        split_bf16(x.x, ph.h[0], pl.h[0]);
        split_bf16(x.y, ph.h[1], pl.h[1]);
        size_t o = ((size_t)row * D + col2) >> 1;
        dstH[o] = ph.u; dstL[o] = pl.u;
    }
}

// ================= fused layer kernel =================
// CTA tile 128(m) x 128(n), K=256. 8 warps, warp tile 32x64.
// Prologue: BN finalize (redundant/CTA) + fold a*W -> smem bf16 hi/lo + bias fold.
// Mainloop: 4 k-chunks of 64, double-buffered cp.async A; 3-pass split MMA.
// Epilogue: bias + exact gelu (+ stats via shfl reduce, + hi/lo split store).
template <bool NORM, bool FINAL>
__global__ __launch_bounds__(256, 1)
void layer_kernel(const __nv_bfloat16* __restrict__ Ahi,
                  const __nv_bfloat16* __restrict__ Alo,
                  const float* __restrict__ W,      // [k][n] fp32, 256x256
                  const float* __restrict__ bvec,   // this layer's b
                  const float* __restrict__ gamma,
                  const float* __restrict__ beta,
                  int sl, int so,
                  __nv_bfloat16* __restrict__ Ohi,
                  __nv_bfloat16* __restrict__ Olo,
                  float* __restrict__ Ofp)
{
    extern __shared__ char smem[];
    const uint32_t sb = smem_u32(smem);
    const int tid  = threadIdx.x;
    const int lane = tid & 31;
    const int wid  = tid >> 5;
    const int wm   = wid >> 1;        // 0..3
    const int wn   = wid & 1;         // 0..1
    const int n0   = blockIdx.x * 128;
    const int m0   = blockIdx.y * 128;

    auto load_stage = [&](int ch, int s) {
        const uint32_t st = sb + OFF_A + s * A_STG;
#pragma unroll
        for (int i = 0; i < 4; i++) {
            int o = tid + i * 256;
            int row = o >> 3, seg = o & 7;
            cp16(st + row * ASTR + seg * 16,
                 Ahi + (size_t)(m0 + row) * D + ch * 64 + seg * 8);
        }
#pragma unroll
        for (int i = 0; i < 4; i++) {
            int o = tid + i * 256;
            int row = o >> 3, seg = o & 7;
            cp16(st + A_PLANE + row * ASTR + seg * 16,
                 Alo + (size_t)(m0 + row) * D + ch * 64 + seg * 8);
        }
    };

    // prefetch A chunks 0,1 first (independent of fold work)
    load_stage(0, 0); CP_COMMIT;
    load_stage(1, 1); CP_COMMIT;

    float* sA    = (float*)(smem + OFF_SA);
    float* sC    = (float*)(smem + OFF_SC);
    float* sBias = (float*)(smem + OFF_BIAS);
    float* sSum  = (float*)(smem + OFF_SUM);
    float* sSq   = (float*)(smem + OFF_SQ);

    if (NORM) {
        const float inv_m = 1.0f / (float)MT;
        float mu  = g_sum[sl * D + tid] * inv_m;
        float var = g_sq[sl * D + tid] * inv_m - mu * mu;
        float a = rsqrtf(var + 1e-5f) * gamma[tid];
        sA[tid] = a;
        sC[tid] = beta[tid] - mu * a;
    }
    if (tid < 128) { sBias[tid] = bvec[n0 + tid]; sSum[tid] = 0.f; sSq[tid] = 0.f; }
    __syncthreads();

    // ---- fold W into smem B (bf16 hi/lo), accumulate c·W into bias ----
    {
        const int nq = tid & 31;       // 4-col group within n-half
        const int kr = tid >> 5;       // k row start
        float cp0 = 0.f, cp1 = 0.f, cp2 = 0.f, cp3 = 0.f;
#pragma unroll 4
        for (int kk = 0; kk < 32; kk++) {
            int k = kr + kk * 8;
            float4 w = *(const float4*)(W + (size_t)k * D + n0 + nq * 4);
            if (NORM) {
                float a = sA[k], c = sC[k];
                cp0 = fmaf(c, w.x, cp0); cp1 = fmaf(c, w.y, cp1);
                cp2 = fmaf(c, w.z, cp2); cp3 = fmaf(c, w.w, cp3);
                w.x *= a; w.y *= a; w.z *= a; w.w *= a;
            }
            union { __nv_bfloat16 b[4]; uint2 u; } ph, pl;
            split_bf16(w.x, ph.b[0], pl.b[0]);
            split_bf16(w.y, ph.b[1], pl.b[1]);
            split_bf16(w.z, ph.b[2], pl.b[2]);
            split_bf16(w.w, ph.b[3], pl.b[3]);
            *(uint2*)(smem + OFF_B + k * BSTR + nq * 8)           = ph.u;
            *(uint2*)(smem + OFF_B + B_PLANE + k * BSTR + nq * 8) = pl.u;
        }
        if (NORM) {
            atomicAdd(&sBias[nq * 4 + 0], cp0);
            atomicAdd(&sBias[nq * 4 + 1], cp1);
            atomicAdd(&sBias[nq * 4 + 2], cp2);
            atomicAdd(&sBias[nq * 4 + 3], cp3);
        }
    }

    float acc[2][8][4];
#pragma unroll
    for (int mt = 0; mt < 2; mt++)
#pragma unroll
        for (int n8 = 0; n8 < 8; n8++)
#pragma unroll
            for (int q = 0; q < 4; q++) acc[mt][n8][q] = 0.f;

    const uint32_t aBase = sb + OFF_A + (wm * 32 + (lane & 15)) * ASTR + ((lane >> 4) << 4);
    const uint32_t bBase = sb + OFF_B + (lane & 15) * BSTR
                           + ((wn * 64 + ((lane >> 4) << 3)) << 1);

#pragma unroll 1
    for (int ch = 0; ch < 4; ch++) {
        if (ch < 3) asm volatile("cp.async.wait_group 1;" ::: "memory");
        else        asm volatile("cp.async.wait_group 0;" ::: "memory");
        __syncthreads();
        const uint32_t aCh = aBase + (ch & 1) * A_STG;
        const uint32_t bCh = bBase + ch * 64 * BSTR;
#pragma unroll
        for (int k16 = 0; k16 < 4; k16++) {
            uint32_t ah[2][4], al[2][4], bh[4][4], bl[4][4];
#pragma unroll
            for (int mt = 0; mt < 2; mt++) {
                uint32_t a = aCh + mt * 16 * ASTR + k16 * 32;
                LDSM4(ah[mt], a);
                LDSM4(al[mt], a + A_PLANE);
            }
#pragma unroll
            for (int nt = 0; nt < 4; nt++) {
                uint32_t b = bCh + k16 * 16 * BSTR + nt * 32;
                LDSM4T(bh[nt], b);
                LDSM4T(bl[nt], b + B_PLANE);
            }
#pragma unroll
            for (int mt = 0; mt < 2; mt++)
#pragma unroll
                for (int n8 = 0; n8 < 8; n8++)
                    MMA(acc[mt][n8], ah[mt], bh[n8 >> 1][(n8 & 1) * 2], bh[n8 >> 1][(n8 & 1) * 2 + 1]);
#pragma unroll
            for (int mt = 0; mt < 2; mt++)
#pragma unroll
                for (int n8 = 0; n8 < 8; n8++)
                    MMA(acc[mt][n8], ah[mt], bl[n8 >> 1][(n8 & 1) * 2], bl[n8 >> 1][(n8 & 1) * 2 + 1]);
#pragma unroll
            for (int mt = 0; mt < 2; mt++)
#pragma unroll
                for (int n8 = 0; n8 < 8; n8++)
                    MMA(acc[mt][n8], al[mt], bh[n8 >> 1][(n8 & 1) * 2], bh[n8 >> 1][(n8 & 1) * 2 + 1]);
        }
        __syncthreads();
        if (ch < 2) { load_stage(ch + 2, ch & 1); CP_COMMIT; }
    }

    // ---------------- epilogue ----------------
    const int r0base = m0 + wm * 32 + (lane >> 2);
#pragma unroll
    for (int n8 = 0; n8 < 8; n8++) {
        const int colL = wn * 64 + n8 * 8 + (lane & 3) * 2;
        const float b0 = sBias[colL], b1 = sBias[colL + 1];
        float s0 = 0.f, s1 = 0.f, q0 = 0.f, q1 = 0.f;
#pragma unroll
        for (int mt = 0; mt < 2; mt++) {
#pragma unroll
            for (int h = 0; h < 2; h++) {
                float v0 = gelu_exact(acc[mt][n8][h * 2 + 0] + b0);
                float v1 = gelu_exact(acc[mt][n8][h * 2 + 1] + b1);
                int row = r0base + mt * 16 + h * 8;
                if (FINAL) {
                    *(float2*)(Ofp + (size_t)row * D + n0 + colL) = make_float2(v0, v1);
                } else {
                    s0 += v0; s1 += v1; q0 += v0 * v0; q1 += v1 * v1;
                    union { __nv_bfloat16 hh[2]; uint32_t u; } ph, pl;
                    split_bf16(v0, ph.hh[0], pl.hh[0]);
                    split_bf16(v1, ph.hh[1], pl.hh[1]);
                    size_t o = ((size_t)row * D + n0 + colL) >> 1;
                    ((uint32_t*)Ohi)[o] = ph.u;
                    ((uint32_t*)Olo)[o] = pl.u;
                }
            }
        }
        if (!FINAL) {
#pragma unroll
            for (int off = 4; off < 32; off <<= 1) {
                s0 += __shfl_xor_sync(0xFFFFFFFFu, s0, off);
                s1 += __shfl_xor_sync(0xFFFFFFFFu, s1, off);
                q0 += __shfl_xor_sync(0xFFFFFFFFu, q0, off);
                q1 += __shfl_xor_sync(0xFFFFFFFFu, q1, off);
            }
            if (lane < 4) {
                int c = wn * 64 + n8 * 8 + lane * 2;
                atomicAdd(&sSum[c],     s0);
                atomicAdd(&sSum[c + 1], s1);
                atomicAdd(&sSq[c],      q0);
                atomicAdd(&sSq[c + 1],  q1);
            }
        }
    }

    if (!FINAL) {
        __syncthreads();
        if (tid < 128) {
            atomicAdd(&g_sum[so * D + n0 + tid], sSum[tid]);
            atomicAdd(&g_sq[so * D + n0 + tid],  sSq[tid]);
        }
    }
}

// ================= launch =================
extern "C" void kernel_launch(void* const* d_in, const int* in_sizes, int n_in,
                              void* d_out, int out_size) {
    const int*   ids   = (const int*)d_in[0];
    const float* table = (const float*)d_in[1];
    const float* W1 = (const float*)d_in[2];
    const float* b1 = (const float*)d_in[3];
    const float* W2 = (const float*)d_in[4];
    const float* b2 = (const float*)d_in[5];
    const float* W3 = (const float*)d_in[6];
    const float* b3 = (const float*)d_in[7];
    const float* W4 = (const float*)d_in[8];
    const float* b4 = (const float*)d_in[9];
    const float* g1  = (const float*)d_in[10];
    const float* be1 = (const float*)d_in[11];
    const float* g2  = (const float*)d_in[12];
    const float* be2 = (const float*)d_in[13];
    const float* g3  = (const float*)d_in[14];
    const float* be3 = (const float*)d_in[15];
    float* out = (float*)d_out;

    __nv_bfloat16 *h0, *l0;
    cudaGetSymbolAddress((void**)&h0, g_actHi);
    cudaGetSymbolAddress((void**)&l0, g_actLo);
    __nv_bfloat16* h1 = h0 + (size_t)MT * D;
    __nv_bfloat16* l1 = l0 + (size_t)MT * D;

    static bool attr_set = false;
    if (!attr_set) {
        cudaFuncSetAttribute(layer_kernel<false, false>,
                             cudaFuncAttributeMaxDynamicSharedMemorySize, SMEM_TOTAL);
        cudaFuncSetAttribute(layer_kernel<true, false>,
                             cudaFuncAttributeMaxDynamicSharedMemorySize, SMEM_TOTAL);
        cudaFuncSetAttribute(layer_kernel<true, true>,
                             cudaFuncAttributeMaxDynamicSharedMemorySize, SMEM_TOTAL);
        attr_set = true;
    }

    dim3 grid(2, 256);

    prep0_kernel<<<256, 256>>>(ids, table);

    layer_kernel<false, false><<<grid, 256, SMEM_TOTAL>>>(
        h0, l0, W1, b1, nullptr, nullptr, 0, 0, h1, l1, nullptr);
    layer_kernel<true, false><<<grid, 256, SMEM_TOTAL>>>(
        h1, l1, W2, b2, g1, be1, 0, 1, h0, l0, nullptr);
    layer_kernel<true, false><<<grid, 256, SMEM_TOTAL>>>(
        h0, l0, W3, b3, g2, be2, 1, 2, h1, l1, nullptr);
    layer_kernel<true, true><<<grid, 256, SMEM_TOTAL>>>(
        h1, l1, W4, b4, g3, be3, 2, -1, nullptr, nullptr, out);
}

// round 7
// speedup vs baseline: 1.2243x; 1.2243x over previous
#include <cuda_runtime.h>
#include <cuda_bf16.h>
#include <math.h>
#include <stdint.h>

constexpr int MT = 32768;
constexpr int D  = 256;

// ---------------- smem layout (bytes) ----------------
constexpr int OFF_BIAS = 0;      // float[128]
constexpr int OFF_SUM  = 512;    // float[128]
constexpr int OFF_SQ   = 1024;   // float[128]
constexpr int OFF_STG  = 2048;
constexpr int ASTR     = 80;     // 32 bf16 (64B) + 16B pad -> all 32 banks distinct
constexpr int PLANE    = 128 * ASTR;      // 10240
constexpr int T_AHI = 0, T_ALO = PLANE, T_BHI = 2 * PLANE, T_BLO = 3 * PLANE;
constexpr int STG_BYTES = 4 * PLANE;      // 40960
constexpr int SMEM_TOTAL = OFF_STG + 2 * STG_BYTES;   // 83968

// ---------------- device scratch ----------------
__device__ __nv_bfloat16 g_actHi[2][(size_t)MT * D];
__device__ __nv_bfloat16 g_actLo[2][(size_t)MT * D];
__device__ __nv_bfloat16 g_Whi[4][D * D];   // [n][k] folded hi
__device__ __nv_bfloat16 g_Wlo[4][D * D];   // [n][k] folded lo
__device__ float g_bias[4][D];
__device__ float g_sum[3 * D];
__device__ float g_sq[3 * D];

// ---------------- helpers ----------------
__device__ __forceinline__ uint32_t smem_u32(const void* p) {
    return (uint32_t)__cvta_generic_to_shared(p);
}
__device__ __forceinline__ void cp16(uint32_t sdst, const void* gsrc) {
    asm volatile("cp.async.cg.shared.global [%0], [%1], 16;\n" :: "r"(sdst), "l"(gsrc));
}
#define CP_COMMIT asm volatile("cp.async.commit_group;\n" ::: "memory")

__device__ __forceinline__ float gelu_exact(float x) {
    return 0.5f * x * (1.0f + erff(x * 0.70710678118654752f));
}
__device__ __forceinline__ void split_bf16(float x, __nv_bfloat16& hi, __nv_bfloat16& lo) {
    hi = __float2bfloat16(x);
    lo = __float2bfloat16(x - __bfloat162float(hi));
}

#define LDSM4(r, addr) \
    asm volatile("ldmatrix.sync.aligned.m8n8.x4.shared.b16 {%0,%1,%2,%3}, [%4];" \
                 : "=r"((r)[0]), "=r"((r)[1]), "=r"((r)[2]), "=r"((r)[3]) : "r"(addr))
#define MMA(acc, a, b0_, b1_) \
    asm volatile("mma.sync.aligned.m16n8k16.row.col.f32.bf16.bf16.f32 " \
                 "{%0,%1,%2,%3}, {%4,%5,%6,%7}, {%8,%9}, {%0,%1,%2,%3};" \
                 : "+f"((acc)[0]), "+f"((acc)[1]), "+f"((acc)[2]), "+f"((acc)[3]) \
                 : "r"((a)[0]), "r"((a)[1]), "r"((a)[2]), "r"((a)[3]), \
                   "r"(b0_), "r"(b1_))

// ================= prep0: zero stats + gather/split + W1 fold =================
__global__ __launch_bounds__(256)
void prep0_kernel(const int* __restrict__ ids, const float* __restrict__ table,
                  const float* __restrict__ W1, const float* __restrict__ b1) {
    const int tid = threadIdx.x, blk = blockIdx.x;
    if (blk < 256) {
        // gather + split 128 rows
        const int col2 = (tid & 127) * 2;
        const int rsub = tid >> 7;
        uint32_t* dstH = (uint32_t*)g_actHi[0];
        uint32_t* dstL = (uint32_t*)g_actLo[0];
#pragma unroll 4
        for (int i = 0; i < 64; i++) {
            int row = blk * 128 + rsub + i * 2;
            int id  = __ldg(ids + row);
            float2 x = *(const float2*)(table + (size_t)id * D + col2);
            union { __nv_bfloat16 h[2]; uint32_t u; } ph, pl;
            split_bf16(x.x, ph.h[0], pl.h[0]);
            split_bf16(x.y, ph.h[1], pl.h[1]);
            size_t o = ((size_t)row * D + col2) >> 1;
            dstH[o] = ph.u; dstL[o] = pl.u;
        }
    } else {
        const int n = blk - 256;
        if (blk == 256) {
            for (int i = tid; i < 3 * D; i += 256) { g_sum[i] = 0.f; g_sq[i] = 0.f; }
        }
        float w = W1[(size_t)tid * D + n];
        __nv_bfloat16 hi, lo; split_bf16(w, hi, lo);
        g_Whi[0][n * D + tid] = hi;
        g_Wlo[0][n * D + tid] = lo;
        if (tid == 0) g_bias[0][n] = b1[n];
    }
}

// ================= per-layer fold: BN finalize + fold into [n][k] bf16 planes =================
__global__ __launch_bounds__(256)
void fold_kernel(const float* __restrict__ W, const float* __restrict__ b,
                 const float* __restrict__ gamma, const float* __restrict__ beta,
                 int L, int sl) {
    __shared__ float red[256];
    const int n = blockIdx.x, k = threadIdx.x;
    const float inv_m = 1.0f / (float)MT;
    float mu  = g_sum[sl * D + k] * inv_m;
    float var = g_sq[sl * D + k] * inv_m - mu * mu;
    float a = rsqrtf(var + 1e-5f) * gamma[k];
    float c = beta[k] - mu * a;
    float w = W[(size_t)k * D + n];
    __nv_bfloat16 hi, lo; split_bf16(a * w, hi, lo);
    g_Whi[L][n * D + k] = hi;
    g_Wlo[L][n * D + k] = lo;
    red[k] = c * w;
    __syncthreads();
#pragma unroll
    for (int s = 128; s > 0; s >>= 1) {
        if (k < s) red[k] += red[k + s];
        __syncthreads();
    }
    if (k == 0) g_bias[L][n] = b[n] + red[0];
}

// ================= layer kernel: 128x128 tile, k32 chunks, 2 CTAs/SM =================
template <bool FINAL>
__global__ __launch_bounds__(256, 2)
void layer_kernel(const __nv_bfloat16* __restrict__ Ahi,
                  const __nv_bfloat16* __restrict__ Alo,
                  int wl, int so,
                  __nv_bfloat16* __restrict__ Ohi,
                  __nv_bfloat16* __restrict__ Olo,
                  float* __restrict__ Ofp)
{
    extern __shared__ char smem[];
    const uint32_t sb = smem_u32(smem);
    const int tid  = threadIdx.x;
    const int lane = tid & 31;
    const int wid  = tid >> 5;
    const int wm   = wid >> 1;
    const int wn   = wid & 1;
    const int n0   = blockIdx.x * 128;
    const int m0   = blockIdx.y * 128;

    const __nv_bfloat16* __restrict__ Whi = g_Whi[wl];
    const __nv_bfloat16* __restrict__ Wlo = g_Wlo[wl];

    const int lrow = tid >> 2;            // 0..63 per half-iter
    const int lseg = tid & 3;             // 16B seg within 64B
    auto load_stage = [&](int ch, int s) {
        const uint32_t st = sb + OFF_STG + s * STG_BYTES;
        const int kof = ch * 32 + lseg * 8;
#pragma unroll
        for (int i = 0; i < 2; i++) {
            int row = lrow + i * 64;
            uint32_t d = row * ASTR + lseg * 16;
            size_t ga = (size_t)(m0 + row) * D + kof;
            cp16(st + T_AHI + d, Ahi + ga);
            cp16(st + T_ALO + d, Alo + ga);
            size_t gb = (size_t)(n0 + row) * D + kof;
            cp16(st + T_BHI + d, Whi + gb);
            cp16(st + T_BLO + d, Wlo + gb);
        }
    };

    load_stage(0, 0); CP_COMMIT;
    load_stage(1, 1); CP_COMMIT;

    float* sBias = (float*)(smem + OFF_BIAS);
    float* sSum  = (float*)(smem + OFF_SUM);
    float* sSq   = (float*)(smem + OFF_SQ);
    if (tid < 128) {
        sBias[tid] = g_bias[wl][n0 + tid];
        sSum[tid] = 0.f; sSq[tid] = 0.f;
    }

    float acc[2][8][4];
#pragma unroll
    for (int mt = 0; mt < 2; mt++)
#pragma unroll
        for (int n8 = 0; n8 < 8; n8++)
#pragma unroll
            for (int q = 0; q < 4; q++) acc[mt][n8][q] = 0.f;

    // ldmatrix base offsets (within a stage)
    const uint32_t aOff = (wm * 32 + (lane & 15)) * ASTR + ((lane >> 4) << 4);
    const uint32_t bOff = (wn * 64 + (lane & 7) + ((lane >> 4) << 3)) * ASTR
                          + (((lane >> 3) & 1) << 4);

#pragma unroll 1
    for (int ch = 0; ch < 8; ch++) {
        if (ch < 7) asm volatile("cp.async.wait_group 1;" ::: "memory");
        else        asm volatile("cp.async.wait_group 0;" ::: "memory");
        __syncthreads();
        const uint32_t st = sb + OFF_STG + (ch & 1) * STG_BYTES;
#pragma unroll
        for (int k16 = 0; k16 < 2; k16++) {
            uint32_t ah[2][4], al[2][4];
#pragma unroll
            for (int mt = 0; mt < 2; mt++) {
                uint32_t a = st + T_AHI + aOff + mt * 16 * ASTR + k16 * 32;
                LDSM4(ah[mt], a);
                LDSM4(al[mt], a + PLANE);
            }
#pragma unroll
            for (int nt = 0; nt < 4; nt++) {
                uint32_t bh[4], bl[4];
                uint32_t b = st + T_BHI + bOff + nt * 16 * ASTR + k16 * 32;
                LDSM4(bh, b);
                LDSM4(bl, b + PLANE);
#pragma unroll
                for (int mt = 0; mt < 2; mt++) {
#pragma unroll
                    for (int j = 0; j < 2; j++) {
                        float* a4 = acc[mt][nt * 2 + j];
                        MMA(a4, ah[mt], bh[j * 2], bh[j * 2 + 1]);
                        MMA(a4, ah[mt], bl[j * 2], bl[j * 2 + 1]);
                        MMA(a4, al[mt], bh[j * 2], bh[j * 2 + 1]);
                    }
                }
            }
        }
        __syncthreads();
        if (ch < 6) { load_stage(ch + 2, ch & 1); CP_COMMIT; }
    }

    // ---------------- epilogue ----------------
    const int r0base = m0 + wm * 32 + (lane >> 2);
#pragma unroll
    for (int n8 = 0; n8 < 8; n8++) {
        const int colL = wn * 64 + n8 * 8 + (lane & 3) * 2;
        const float b0 = sBias[colL], b1 = sBias[colL + 1];
        float s0 = 0.f, s1 = 0.f, q0 = 0.f, q1 = 0.f;
#pragma unroll
        for (int mt = 0; mt < 2; mt++) {
#pragma unroll
            for (int h = 0; h < 2; h++) {
                float v0 = gelu_exact(acc[mt][n8][h * 2 + 0] + b0);
                float v1 = gelu_exact(acc[mt][n8][h * 2 + 1] + b1);
                int row = r0base + mt * 16 + h * 8;
                if (FINAL) {
                    *(float2*)(Ofp + (size_t)row * D + n0 + colL) = make_float2(v0, v1);
                } else {
                    s0 += v0; s1 += v1; q0 += v0 * v0; q1 += v1 * v1;
                    union { __nv_bfloat16 hh[2]; uint32_t u; } ph, pl;
                    split_bf16(v0, ph.hh[0], pl.hh[0]);
                    split_bf16(v1, ph.hh[1], pl.hh[1]);
                    size_t o = ((size_t)row * D + n0 + colL) >> 1;
                    ((uint32_t*)Ohi)[o] = ph.u;
                    ((uint32_t*)Olo)[o] = pl.u;
                }
            }
        }
        if (!FINAL) {
#pragma unroll
            for (int off = 4; off < 32; off <<= 1) {
                s0 += __shfl_xor_sync(0xFFFFFFFFu, s0, off);
                s1 += __shfl_xor_sync(0xFFFFFFFFu, s1, off);
                q0 += __shfl_xor_sync(0xFFFFFFFFu, q0, off);
                q1 += __shfl_xor_sync(0xFFFFFFFFu, q1, off);
            }
            if (lane < 4) {
                int c = wn * 64 + n8 * 8 + lane * 2;
                atomicAdd(&sSum[c],     s0);
                atomicAdd(&sSum[c + 1], s1);
                atomicAdd(&sSq[c],      q0);
                atomicAdd(&sSq[c + 1],  q1);
            }
        }
    }

    if (!FINAL) {
        __syncthreads();
        if (tid < 128) {
            atomicAdd(&g_sum[so * D + n0 + tid], sSum[tid]);
            atomicAdd(&g_sq[so * D + n0 + tid],  sSq[tid]);
        }
    }
}

// ================= launch =================
extern "C" void kernel_launch(void* const* d_in, const int* in_sizes, int n_in,
                              void* d_out, int out_size) {
    const int*   ids   = (const int*)d_in[0];
    const float* table = (const float*)d_in[1];
    const float* W1 = (const float*)d_in[2];
    const float* b1 = (const float*)d_in[3];
    const float* W2 = (const float*)d_in[4];
    const float* b2 = (const float*)d_in[5];
    const float* W3 = (const float*)d_in[6];
    const float* b3 = (const float*)d_in[7];
    const float* W4 = (const float*)d_in[8];
    const float* b4 = (const float*)d_in[9];
    const float* g1  = (const float*)d_in[10];
    const float* be1 = (const float*)d_in[11];
    const float* g2  = (const float*)d_in[12];
    const float* be2 = (const float*)d_in[13];
    const float* g3  = (const float*)d_in[14];
    const float* be3 = (const float*)d_in[15];
    float* out = (float*)d_out;

    __nv_bfloat16 *h0, *l0;
    cudaGetSymbolAddress((void**)&h0, g_actHi);
    cudaGetSymbolAddress((void**)&l0, g_actLo);
    __nv_bfloat16* h1 = h0 + (size_t)MT * D;
    __nv_bfloat16* l1 = l0 + (size_t)MT * D;

    static bool attr_set = false;
    if (!attr_set) {
        cudaFuncSetAttribute(layer_kernel<false>,
                             cudaFuncAttributeMaxDynamicSharedMemorySize, SMEM_TOTAL);
        cudaFuncSetAttribute(layer_kernel<true>,
                             cudaFuncAttributeMaxDynamicSharedMemorySize, SMEM_TOTAL);
        attr_set = true;
    }

    dim3 grid(2, 256);

    prep0_kernel<<<512, 256>>>(ids, table, W1, b1);

    layer_kernel<false><<<grid, 256, SMEM_TOTAL>>>(h0, l0, 0, 0, h1, l1, nullptr);
    fold_kernel<<<256, 256>>>(W2, b2, g1, be1, 1, 0);
    layer_kernel<false><<<grid, 256, SMEM_TOTAL>>>(h1, l1, 1, 1, h0, l0, nullptr);
    fold_kernel<<<256, 256>>>(W3, b3, g2, be2, 2, 1);
    layer_kernel<false><<<grid, 256, SMEM_TOTAL>>>(h0, l0, 2, 2, h1, l1, nullptr);
    fold_kernel<<<256, 256>>>(W4, b4, g3, be3, 3, 2);
    layer_kernel<true><<<grid, 256, SMEM_TOTAL>>>(h1, l1, 3, -1, nullptr, nullptr, out);
}

// round 8
// speedup vs baseline: 1.2363x; 1.0098x over previous
#include <cuda_runtime.h>
#include <cuda_bf16.h>
#include <math.h>
#include <stdint.h>

constexpr int MT = 32768;
constexpr int D  = 256;

// ---------------- smem layout (bytes) ----------------
constexpr int OFF_BIAS = 0;      // float[128]
constexpr int OFF_SUM  = 512;    // float[128]
constexpr int OFF_SQ   = 1024;   // float[128]
constexpr int OFF_STG  = 2048;
// plane: 128 rows x 64B (k32 bf16), XOR-swizzled 16B segs, no padding
constexpr int PLANE     = 128 * 64;            // 8192
constexpr int T_AHI = 0, T_ALO = PLANE, T_BHI = 2 * PLANE, T_BLO = 3 * PLANE;
constexpr int STG_BYTES = 4 * PLANE;           // 32768
constexpr int NSTAGE    = 3;
constexpr int SMEM_TOTAL = OFF_STG + NSTAGE * STG_BYTES;   // 100352

// ---------------- device scratch ----------------
__device__ __nv_bfloat16 g_actHi[2][(size_t)MT * D];
__device__ __nv_bfloat16 g_actLo[2][(size_t)MT * D];
__device__ __nv_bfloat16 g_Whi[4][D * D];   // [n][k] folded hi
__device__ __nv_bfloat16 g_Wlo[4][D * D];   // [n][k] folded lo
__device__ float g_bias[4][D];
__device__ float g_sum[3 * D];
__device__ float g_sq[3 * D];

// ---------------- helpers ----------------
__device__ __forceinline__ uint32_t smem_u32(const void* p) {
    return (uint32_t)__cvta_generic_to_shared(p);
}
__device__ __forceinline__ void cp16(uint32_t sdst, const void* gsrc) {
    asm volatile("cp.async.cg.shared.global [%0], [%1], 16;\n" :: "r"(sdst), "l"(gsrc));
}
#define CP_COMMIT asm volatile("cp.async.commit_group;\n" ::: "memory")

__device__ __forceinline__ float gelu_exact(float x) {
    return 0.5f * x * (1.0f + erff(x * 0.70710678118654752f));
}
__device__ __forceinline__ void split_bf16(float x, __nv_bfloat16& hi, __nv_bfloat16& lo) {
    hi = __float2bfloat16(x);
    lo = __float2bfloat16(x - __bfloat162float(hi));
}

#define LDSM4(r, addr) \
    asm volatile("ldmatrix.sync.aligned.m8n8.x4.shared.b16 {%0,%1,%2,%3}, [%4];" \
                 : "=r"((r)[0]), "=r"((r)[1]), "=r"((r)[2]), "=r"((r)[3]) : "r"(addr))
#define MMA(acc, a, b0_, b1_) \
    asm volatile("mma.sync.aligned.m16n8k16.row.col.f32.bf16.bf16.f32 " \
                 "{%0,%1,%2,%3}, {%4,%5,%6,%7}, {%8,%9}, {%0,%1,%2,%3};" \
                 : "+f"((acc)[0]), "+f"((acc)[1]), "+f"((acc)[2]), "+f"((acc)[3]) \
                 : "r"((a)[0]), "r"((a)[1]), "r"((a)[2]), "r"((a)[3]), \
                   "r"(b0_), "r"(b1_))

// ================= prep0: zero stats + gather/split + W1 fold =================
__global__ __launch_bounds__(256)
void prep0_kernel(const int* __restrict__ ids, const float* __restrict__ table,
                  const float* __restrict__ W1, const float* __restrict__ b1) {
    const int tid = threadIdx.x, blk = blockIdx.x;
    if (blk < 256) {
        const int col2 = (tid & 127) * 2;
        const int rsub = tid >> 7;
        uint32_t* dstH = (uint32_t*)g_actHi[0];
        uint32_t* dstL = (uint32_t*)g_actLo[0];
#pragma unroll 4
        for (int i = 0; i < 64; i++) {
            int row = blk * 128 + rsub + i * 2;
            int id  = __ldg(ids + row);
            float2 x = *(const float2*)(table + (size_t)id * D + col2);
            union { __nv_bfloat16 h[2]; uint32_t u; } ph, pl;
            split_bf16(x.x, ph.h[0], pl.h[0]);
            split_bf16(x.y, ph.h[1], pl.h[1]);
            size_t o = ((size_t)row * D + col2) >> 1;
            dstH[o] = ph.u; dstL[o] = pl.u;
        }
    } else {
        const int n = blk - 256;
        if (blk == 256) {
            for (int i = tid; i < 3 * D; i += 256) { g_sum[i] = 0.f; g_sq[i] = 0.f; }
        }
        float w = W1[(size_t)tid * D + n];
        __nv_bfloat16 hi, lo; split_bf16(w, hi, lo);
        g_Whi[0][n * D + tid] = hi;
        g_Wlo[0][n * D + tid] = lo;
        if (tid == 0) g_bias[0][n] = b1[n];
    }
}

// ================= per-layer fold =================
__global__ __launch_bounds__(256)
void fold_kernel(const float* __restrict__ W, const float* __restrict__ b,
                 const float* __restrict__ gamma, const float* __restrict__ beta,
                 int L, int sl) {
    __shared__ float red[256];
    const int n = blockIdx.x, k = threadIdx.x;
    const float inv_m = 1.0f / (float)MT;
    float mu  = g_sum[sl * D + k] * inv_m;
    float var = g_sq[sl * D + k] * inv_m - mu * mu;
    float a = rsqrtf(var + 1e-5f) * gamma[k];
    float c = beta[k] - mu * a;
    float w = W[(size_t)k * D + n];
    __nv_bfloat16 hi, lo; split_bf16(a * w, hi, lo);
    g_Whi[L][n * D + k] = hi;
    g_Wlo[L][n * D + k] = lo;
    red[k] = c * w;
    __syncthreads();
#pragma unroll
    for (int s = 128; s > 0; s >>= 1) {
        if (k < s) red[k] += red[k + s];
        __syncthreads();
    }
    if (k == 0) g_bias[L][n] = b[n] + red[0];
}

// ================= layer kernel: 128x128 tile, 3-stage k32 pipeline =================
template <bool FINAL>
__global__ __launch_bounds__(256, 2)
void layer_kernel(const __nv_bfloat16* __restrict__ Ahi,
                  const __nv_bfloat16* __restrict__ Alo,
                  int wl, int so,
                  __nv_bfloat16* __restrict__ Ohi,
                  __nv_bfloat16* __restrict__ Olo,
                  float* __restrict__ Ofp)
{
    extern __shared__ char smem[];
    const uint32_t sb = smem_u32(smem);
    const int tid  = threadIdx.x;
    const int lane = tid & 31;
    const int wid  = tid >> 5;
    const int wm   = wid >> 1;
    const int wn   = wid & 1;
    const int n0   = blockIdx.x * 128;
    const int m0   = blockIdx.y * 128;

    const __nv_bfloat16* __restrict__ Whi = g_Whi[wl];
    const __nv_bfloat16* __restrict__ Wlo = g_Wlo[wl];

    // cp.async mapping: thread -> (row = tid>>1, segs {sp, sp+1})
    const int lrow = tid >> 1;
    const int lsp  = (tid & 1) * 2;
    const uint32_t lkey = (uint32_t)((lrow >> 1) & 3);

    auto load_stage = [&](int ch, int s) {
        const uint32_t st = sb + OFF_STG + s * STG_BYTES;
        const int kof = ch * 32;
        const size_t ga = (size_t)(m0 + lrow) * D + kof;
        const size_t gb = (size_t)(n0 + lrow) * D + kof;
        const uint32_t rbase = st + lrow * 64;
#pragma unroll
        for (int i = 0; i < 2; i++) {
            const uint32_t seg = lsp + i;
            const uint32_t d = rbase + ((seg ^ lkey) << 4);
            cp16(d + T_AHI, Ahi + ga + seg * 8);
            cp16(d + T_ALO, Alo + ga + seg * 8);
            cp16(d + T_BHI, Whi + gb + seg * 8);
            cp16(d + T_BLO, Wlo + gb + seg * 8);
        }
    };

    load_stage(0, 0); CP_COMMIT;
    load_stage(1, 1); CP_COMMIT;

    float* sBias = (float*)(smem + OFF_BIAS);
    float* sSum  = (float*)(smem + OFF_SUM);
    float* sSq   = (float*)(smem + OFF_SQ);
    if (tid < 128) {
        sBias[tid] = g_bias[wl][n0 + tid];
        sSum[tid] = 0.f; sSq[tid] = 0.f;
    }

    float acc[2][8][4];
#pragma unroll
    for (int mt = 0; mt < 2; mt++)
#pragma unroll
        for (int n8 = 0; n8 < 8; n8++)
#pragma unroll
            for (int q = 0; q < 4; q++) acc[mt][n8][q] = 0.f;

    // ldmatrix offsets (XOR-swizzled, k16 toggles bit5)
    const int arow = wm * 32 + (lane & 15);
    const uint32_t aOff = (uint32_t)arow * 64
        + ((((uint32_t)(lane >> 4)) ^ (uint32_t)((arow >> 1) & 3)) << 4);
    const int brow = wn * 64 + (lane & 7) + ((lane >> 4) << 3);
    const uint32_t bOff = (uint32_t)brow * 64
        + ((((uint32_t)((lane >> 3) & 1)) ^ (uint32_t)((brow >> 1) & 3)) << 4);

#pragma unroll 1
    for (int ch = 0; ch < 8; ch++) {
        if (ch < 7) asm volatile("cp.async.wait_group 1;" ::: "memory");
        else        asm volatile("cp.async.wait_group 0;" ::: "memory");
        __syncthreads();
        if (ch + 2 < 8) { load_stage(ch + 2, (ch + 2) % NSTAGE); CP_COMMIT; }

        const uint32_t st = sb + OFF_STG + (ch % NSTAGE) * STG_BYTES;
#pragma unroll
        for (int k16 = 0; k16 < 2; k16++) {
            uint32_t ah[2][4], al[2][4];
#pragma unroll
            for (int mt = 0; mt < 2; mt++) {
                uint32_t a = (st + T_AHI + aOff + mt * 1024) ^ (k16 << 5);
                LDSM4(ah[mt], a);
                LDSM4(al[mt], a + PLANE);
            }
#pragma unroll
            for (int nt = 0; nt < 4; nt++) {
                uint32_t bh[4], bl[4];
                uint32_t b = (st + T_BHI + bOff + nt * 1024) ^ (k16 << 5);
                LDSM4(bh, b);
                LDSM4(bl, b + PLANE);
#pragma unroll
                for (int mt = 0; mt < 2; mt++) {
#pragma unroll
                    for (int j = 0; j < 2; j++) {
                        float* a4 = acc[mt][nt * 2 + j];
                        MMA(a4, ah[mt], bh[j * 2], bh[j * 2 + 1]);
                        MMA(a4, ah[mt], bl[j * 2], bl[j * 2 + 1]);
                        MMA(a4, al[mt], bh[j * 2], bh[j * 2 + 1]);
                    }
                }
            }
        }
    }

    // ---------------- epilogue ----------------
    const int r0base = m0 + wm * 32 + (lane >> 2);
#pragma unroll
    for (int n8 = 0; n8 < 8; n8++) {
        const int colL = wn * 64 + n8 * 8 + (lane & 3) * 2;
        const float b0 = sBias[colL], b1 = sBias[colL + 1];
        float s0 = 0.f, s1 = 0.f, q0 = 0.f, q1 = 0.f;
#pragma unroll
        for (int mt = 0; mt < 2; mt++) {
#pragma unroll
            for (int h = 0; h < 2; h++) {
                float v0 = gelu_exact(acc[mt][n8][h * 2 + 0] + b0);
                float v1 = gelu_exact(acc[mt][n8][h * 2 + 1] + b1);
                int row = r0base + mt * 16 + h * 8;
                if (FINAL) {
                    *(float2*)(Ofp + (size_t)row * D + n0 + colL) = make_float2(v0, v1);
                } else {
                    s0 += v0; s1 += v1; q0 += v0 * v0; q1 += v1 * v1;
                    union { __nv_bfloat16 hh[2]; uint32_t u; } ph, pl;
                    split_bf16(v0, ph.hh[0], pl.hh[0]);
                    split_bf16(v1, ph.hh[1], pl.hh[1]);
                    size_t o = ((size_t)row * D + n0 + colL) >> 1;
                    ((uint32_t*)Ohi)[o] = ph.u;
                    ((uint32_t*)Olo)[o] = pl.u;
                }
            }
        }
        if (!FINAL) {
#pragma unroll
            for (int off = 4; off < 32; off <<= 1) {
                s0 += __shfl_xor_sync(0xFFFFFFFFu, s0, off);
                s1 += __shfl_xor_sync(0xFFFFFFFFu, s1, off);
                q0 += __shfl_xor_sync(0xFFFFFFFFu, q0, off);
                q1 += __shfl_xor_sync(0xFFFFFFFFu, q1, off);
            }
            if (lane < 4) {
                int c = wn * 64 + n8 * 8 + lane * 2;
                atomicAdd(&sSum[c],     s0);
                atomicAdd(&sSum[c + 1], s1);
                atomicAdd(&sSq[c],      q0);
                atomicAdd(&sSq[c + 1],  q1);
            }
        }
    }

    if (!FINAL) {
        __syncthreads();
        if (tid < 128) {
            atomicAdd(&g_sum[so * D + n0 + tid], sSum[tid]);
            atomicAdd(&g_sq[so * D + n0 + tid],  sSq[tid]);
        }
    }
}

// ================= launch =================
extern "C" void kernel_launch(void* const* d_in, const int* in_sizes, int n_in,
                              void* d_out, int out_size) {
    const int*   ids   = (const int*)d_in[0];
    const float* table = (const float*)d_in[1];
    const float* W1 = (const float*)d_in[2];
    const float* b1 = (const float*)d_in[3];
    const float* W2 = (const float*)d_in[4];
    const float* b2 = (const float*)d_in[5];
    const float* W3 = (const float*)d_in[6];
    const float* b3 = (const float*)d_in[7];
    const float* W4 = (const float*)d_in[8];
    const float* b4 = (const float*)d_in[9];
    const float* g1  = (const float*)d_in[10];
    const float* be1 = (const float*)d_in[11];
    const float* g2  = (const float*)d_in[12];
    const float* be2 = (const float*)d_in[13];
    const float* g3  = (const float*)d_in[14];
    const float* be3 = (const float*)d_in[15];
    float* out = (float*)d_out;

    __nv_bfloat16 *h0, *l0;
    cudaGetSymbolAddress((void**)&h0, g_actHi);
    cudaGetSymbolAddress((void**)&l0, g_actLo);
    __nv_bfloat16* h1 = h0 + (size_t)MT * D;
    __nv_bfloat16* l1 = l0 + (size_t)MT * D;

    static bool attr_set = false;
    if (!attr_set) {
        cudaFuncSetAttribute(layer_kernel<false>,
                             cudaFuncAttributeMaxDynamicSharedMemorySize, SMEM_TOTAL);
        cudaFuncSetAttribute(layer_kernel<true>,
                             cudaFuncAttributeMaxDynamicSharedMemorySize, SMEM_TOTAL);
        attr_set = true;
    }

    dim3 grid(2, 256);

    prep0_kernel<<<512, 256>>>(ids, table, W1, b1);

    layer_kernel<false><<<grid, 256, SMEM_TOTAL>>>(h0, l0, 0, 0, h1, l1, nullptr);
    fold_kernel<<<256, 256>>>(W2, b2, g1, be1, 1, 0);
    layer_kernel<false><<<grid, 256, SMEM_TOTAL>>>(h1, l1, 1, 1, h0, l0, nullptr);
    fold_kernel<<<256, 256>>>(W3, b3, g2, be2, 2, 1);
    layer_kernel<false><<<grid, 256, SMEM_TOTAL>>>(h0, l0, 2, 2, h1, l1, nullptr);
    fold_kernel<<<256, 256>>>(W4, b4, g3, be3, 3, 2);
    layer_kernel<true><<<grid, 256, SMEM_TOTAL>>>(h1, l1, 3, -1, nullptr, nullptr, out);
}

// round 9
// speedup vs baseline: 1.5157x; 1.2259x over previous
#include <cuda_runtime.h>
#include <cuda_fp16.h>
#include <math.h>
#include <stdint.h>

constexpr int MT = 32768;
constexpr int D  = 256;

// ---------------- smem layout (bytes) ----------------
constexpr int OFF_BIAS = 0;      // float[128]
constexpr int OFF_SUM  = 512;    // float[128]
constexpr int OFF_SQ   = 1024;   // float[128]
constexpr int OFF_STG  = 2048;
// plane: 128 rows x 64B (k32 fp16), XOR-swizzled 16B segs, no padding
constexpr int PLANE     = 128 * 64;            // 8192
constexpr int T_AHI = 0, T_ALO = PLANE, T_B = 2 * PLANE;
constexpr int STG_BYTES = 3 * PLANE;           // 24576
constexpr int NSTAGE    = 4;
constexpr int SMEM_TOTAL = OFF_STG + NSTAGE * STG_BYTES;   // 100352

// ---------------- device scratch ----------------
__device__ __half g_actHi[2][(size_t)MT * D];
__device__ __half g_actLo[2][(size_t)MT * D];
__device__ __half g_W[4][D * D];     // [n][k] folded fp16 weights (single plane)
__device__ float g_bias[4][D];
__device__ float g_sum[3 * D];
__device__ float g_sq[3 * D];

// ---------------- helpers ----------------
__device__ __forceinline__ uint32_t smem_u32(const void* p) {
    return (uint32_t)__cvta_generic_to_shared(p);
}
__device__ __forceinline__ void cp16(uint32_t sdst, const void* gsrc) {
    asm volatile("cp.async.cg.shared.global [%0], [%1], 16;\n" :: "r"(sdst), "l"(gsrc));
}
#define CP_COMMIT asm volatile("cp.async.commit_group;\n" ::: "memory")

__device__ __forceinline__ float gelu_exact(float x) {
    return 0.5f * x * (1.0f + erff(x * 0.70710678118654752f));
}
__device__ __forceinline__ void split_f16(float x, __half& hi, __half& lo) {
    hi = __float2half(x);
    lo = __float2half(x - __half2float(hi));
}

#define LDSM4(r, addr) \
    asm volatile("ldmatrix.sync.aligned.m8n8.x4.shared.b16 {%0,%1,%2,%3}, [%4];" \
                 : "=r"((r)[0]), "=r"((r)[1]), "=r"((r)[2]), "=r"((r)[3]) : "r"(addr))
#define MMA(acc, a, b0_, b1_) \
    asm volatile("mma.sync.aligned.m16n8k16.row.col.f32.f16.f16.f32 " \
                 "{%0,%1,%2,%3}, {%4,%5,%6,%7}, {%8,%9}, {%0,%1,%2,%3};" \
                 : "+f"((acc)[0]), "+f"((acc)[1]), "+f"((acc)[2]), "+f"((acc)[3]) \
                 : "r"((a)[0]), "r"((a)[1]), "r"((a)[2]), "r"((a)[3]), \
                   "r"(b0_), "r"(b1_))

// ================= prep0: zero stats + gather/split + W1 fold =================
__global__ __launch_bounds__(256)
void prep0_kernel(const int* __restrict__ ids, const float* __restrict__ table,
                  const float* __restrict__ W1, const float* __restrict__ b1) {
    const int tid = threadIdx.x, blk = blockIdx.x;
    if (blk < 256) {
        const int col2 = (tid & 127) * 2;
        const int rsub = tid >> 7;
        uint32_t* dstH = (uint32_t*)g_actHi[0];
        uint32_t* dstL = (uint32_t*)g_actLo[0];
#pragma unroll 4
        for (int i = 0; i < 64; i++) {
            int row = blk * 128 + rsub + i * 2;
            int id  = __ldg(ids + row);
            float2 x = *(const float2*)(table + (size_t)id * D + col2);
            union { __half h[2]; uint32_t u; } ph, pl;
            split_f16(x.x, ph.h[0], pl.h[0]);
            split_f16(x.y, ph.h[1], pl.h[1]);
            size_t o = ((size_t)row * D + col2) >> 1;
            dstH[o] = ph.u; dstL[o] = pl.u;
        }
    } else {
        const int n = blk - 256;
        if (blk == 256) {
            for (int i = tid; i < 3 * D; i += 256) { g_sum[i] = 0.f; g_sq[i] = 0.f; }
        }
        g_W[0][n * D + tid] = __float2half(W1[(size_t)tid * D + n]);
        if (tid == 0) g_bias[0][n] = b1[n];
    }
}

// ================= per-layer fold =================
__global__ __launch_bounds__(256)
void fold_kernel(const float* __restrict__ W, const float* __restrict__ b,
                 const float* __restrict__ gamma, const float* __restrict__ beta,
                 int L, int sl) {
    __shared__ float red[256];
    const int n = blockIdx.x, k = threadIdx.x;
    const float inv_m = 1.0f / (float)MT;
    float mu  = g_sum[sl * D + k] * inv_m;
    float var = g_sq[sl * D + k] * inv_m - mu * mu;
    float a = rsqrtf(var + 1e-5f) * gamma[k];
    float c = beta[k] - mu * a;
    float w = W[(size_t)k * D + n];
    g_W[L][n * D + k] = __float2half(a * w);
    red[k] = c * w;
    __syncthreads();
#pragma unroll
    for (int s = 128; s > 0; s >>= 1) {
        if (k < s) red[k] += red[k + s];
        __syncthreads();
    }
    if (k == 0) g_bias[L][n] = b[n] + red[0];
}

// ================= layer kernel: 128x128 tile, 4-stage k32 pipeline, 2-pass fp16 =================
template <bool FINAL>
__global__ __launch_bounds__(256, 2)
void layer_kernel(const __half* __restrict__ Ahi,
                  const __half* __restrict__ Alo,
                  int wl, int so,
                  __half* __restrict__ Ohi,
                  __half* __restrict__ Olo,
                  float* __restrict__ Ofp)
{
    extern __shared__ char smem[];
    const uint32_t sb = smem_u32(smem);
    const int tid  = threadIdx.x;
    const int lane = tid & 31;
    const int wid  = tid >> 5;
    const int wm   = wid >> 1;
    const int wn   = wid & 1;
    const int n0   = blockIdx.x * 128;
    const int m0   = blockIdx.y * 128;

    const __half* __restrict__ W = g_W[wl];

    // cp.async mapping: thread -> (row = tid>>1, segs {sp, sp+1})
    const int lrow = tid >> 1;
    const int lsp  = (tid & 1) * 2;
    const uint32_t lkey = (uint32_t)((lrow >> 1) & 3);

    auto load_stage = [&](int ch, int s) {
        const uint32_t st = sb + OFF_STG + s * STG_BYTES;
        const int kof = ch * 32;
        const size_t ga = (size_t)(m0 + lrow) * D + kof;
        const size_t gb = (size_t)(n0 + lrow) * D + kof;
        const uint32_t rbase = st + lrow * 64;
#pragma unroll
        for (int i = 0; i < 2; i++) {
            const uint32_t seg = lsp + i;
            const uint32_t d = rbase + ((seg ^ lkey) << 4);
            cp16(d + T_AHI, Ahi + ga + seg * 8);
            cp16(d + T_ALO, Alo + ga + seg * 8);
            cp16(d + T_B,   W   + gb + seg * 8);
        }
    };

    load_stage(0, 0); CP_COMMIT;
    load_stage(1, 1); CP_COMMIT;
    load_stage(2, 2); CP_COMMIT;

    float* sBias = (float*)(smem + OFF_BIAS);
    float* sSum  = (float*)(smem + OFF_SUM);
    float* sSq   = (float*)(smem + OFF_SQ);
    if (tid < 128) {
        sBias[tid] = g_bias[wl][n0 + tid];
        sSum[tid] = 0.f; sSq[tid] = 0.f;
    }

    float acc[2][8][4];
#pragma unroll
    for (int mt = 0; mt < 2; mt++)
#pragma unroll
        for (int n8 = 0; n8 < 8; n8++)
#pragma unroll
            for (int q = 0; q < 4; q++) acc[mt][n8][q] = 0.f;

    // ldmatrix offsets (XOR-swizzled, k16 toggles bit5)
    const int arow = wm * 32 + (lane & 15);
    const uint32_t aOff = (uint32_t)arow * 64
        + ((((uint32_t)(lane >> 4)) ^ (uint32_t)((arow >> 1) & 3)) << 4);
    const int brow = wn * 64 + (lane & 7) + ((lane >> 4) << 3);
    const uint32_t bOff = (uint32_t)brow * 64
        + ((((uint32_t)((lane >> 3) & 1)) ^ (uint32_t)((brow >> 1) & 3)) << 4);

#pragma unroll 1
    for (int ch = 0; ch < 8; ch++) {
        if (ch < 6)      asm volatile("cp.async.wait_group 2;" ::: "memory");
        else if (ch == 6) asm volatile("cp.async.wait_group 1;" ::: "memory");
        else             asm volatile("cp.async.wait_group 0;" ::: "memory");
        __syncthreads();
        if (ch + 3 < 8) { load_stage(ch + 3, (ch + 3) & 3); CP_COMMIT; }

        const uint32_t st = sb + OFF_STG + (ch & 3) * STG_BYTES;
#pragma unroll
        for (int k16 = 0; k16 < 2; k16++) {
            uint32_t ah[2][4], al[2][4];
#pragma unroll
            for (int mt = 0; mt < 2; mt++) {
                uint32_t a = (st + T_AHI + aOff + mt * 1024) ^ (k16 << 5);
                LDSM4(ah[mt], a);
                LDSM4(al[mt], a + PLANE);
            }
#pragma unroll
            for (int nt = 0; nt < 4; nt++) {
                uint32_t bh[4];
                uint32_t b = (st + T_B + bOff + nt * 1024) ^ (k16 << 5);
                LDSM4(bh, b);
#pragma unroll
                for (int mt = 0; mt < 2; mt++) {
#pragma unroll
                    for (int j = 0; j < 2; j++) {
                        float* a4 = acc[mt][nt * 2 + j];
                        MMA(a4, ah[mt], bh[j * 2], bh[j * 2 + 1]);
                        MMA(a4, al[mt], bh[j * 2], bh[j * 2 + 1]);
                    }
                }
            }
        }
    }

    // ---------------- epilogue ----------------
    const int r0base = m0 + wm * 32 + (lane >> 2);
#pragma unroll
    for (int n8 = 0; n8 < 8; n8++) {
        const int colL = wn * 64 + n8 * 8 + (lane & 3) * 2;
        const float b0 = sBias[colL], b1 = sBias[colL + 1];
        float s0 = 0.f, s1 = 0.f, q0 = 0.f, q1 = 0.f;
#pragma unroll
        for (int mt = 0; mt < 2; mt++) {
#pragma unroll
            for (int h = 0; h < 2; h++) {
                float v0 = gelu_exact(acc[mt][n8][h * 2 + 0] + b0);
                float v1 = gelu_exact(acc[mt][n8][h * 2 + 1] + b1);
                int row = r0base + mt * 16 + h * 8;
                if (FINAL) {
                    *(float2*)(Ofp + (size_t)row * D + n0 + colL) = make_float2(v0, v1);
                } else {
                    s0 += v0; s1 += v1; q0 += v0 * v0; q1 += v1 * v1;
                    union { __half hh[2]; uint32_t u; } ph, pl;
                    split_f16(v0, ph.hh[0], pl.hh[0]);
                    split_f16(v1, ph.hh[1], pl.hh[1]);
                    size_t o = ((size_t)row * D + n0 + colL) >> 1;
                    ((uint32_t*)Ohi)[o] = ph.u;
                    ((uint32_t*)Olo)[o] = pl.u;
                }
            }
        }
        if (!FINAL) {
#pragma unroll
            for (int off = 4; off < 32; off <<= 1) {
                s0 += __shfl_xor_sync(0xFFFFFFFFu, s0, off);
                s1 += __shfl_xor_sync(0xFFFFFFFFu, s1, off);
                q0 += __shfl_xor_sync(0xFFFFFFFFu, q0, off);
                q1 += __shfl_xor_sync(0xFFFFFFFFu, q1, off);
            }
            if (lane < 4) {
                int c = wn * 64 + n8 * 8 + lane * 2;
                atomicAdd(&sSum[c],     s0);
                atomicAdd(&sSum[c + 1], s1);
                atomicAdd(&sSq[c],      q0);
                atomicAdd(&sSq[c + 1],  q1);
            }
        }
    }

    if (!FINAL) {
        __syncthreads();
        if (tid < 128) {
            atomicAdd(&g_sum[so * D + n0 + tid], sSum[tid]);
            atomicAdd(&g_sq[so * D + n0 + tid],  sSq[tid]);
        }
    }
}

// ================= launch =================
extern "C" void kernel_launch(void* const* d_in, const int* in_sizes, int n_in,
                              void* d_out, int out_size) {
    const int*   ids   = (const int*)d_in[0];
    const float* table = (const float*)d_in[1];
    const float* W1 = (const float*)d_in[2];
    const float* b1 = (const float*)d_in[3];
    const float* W2 = (const float*)d_in[4];
    const float* b2 = (const float*)d_in[5];
    const float* W3 = (const float*)d_in[6];
    const float* b3 = (const float*)d_in[7];
    const float* W4 = (const float*)d_in[8];
    const float* b4 = (const float*)d_in[9];
    const float* g1  = (const float*)d_in[10];
    const float* be1 = (const float*)d_in[11];
    const float* g2  = (const float*)d_in[12];
    const float* be2 = (const float*)d_in[13];
    const float* g3  = (const float*)d_in[14];
    const float* be3 = (const float*)d_in[15];
    float* out = (float*)d_out;

    __half *h0, *l0;
    cudaGetSymbolAddress((void**)&h0, g_actHi);
    cudaGetSymbolAddress((void**)&l0, g_actLo);
    __half* h1 = h0 + (size_t)MT * D;
    __half* l1 = l0 + (size_t)MT * D;

    static bool attr_set = false;
    if (!attr_set) {
        cudaFuncSetAttribute(layer_kernel<false>,
                             cudaFuncAttributeMaxDynamicSharedMemorySize, SMEM_TOTAL);
        cudaFuncSetAttribute(layer_kernel<true>,
                             cudaFuncAttributeMaxDynamicSharedMemorySize, SMEM_TOTAL);
        attr_set = true;
    }

    dim3 grid(2, 256);

    prep0_kernel<<<512, 256>>>(ids, table, W1, b1);

    layer_kernel<false><<<grid, 256, SMEM_TOTAL>>>(h0, l0, 0, 0, h1, l1, nullptr);
    fold_kernel<<<256, 256>>>(W2, b2, g1, be1, 1, 0);
    layer_kernel<false><<<grid, 256, SMEM_TOTAL>>>(h1, l1, 1, 1, h0, l0, nullptr);
    fold_kernel<<<256, 256>>>(W3, b3, g2, be2, 2, 1);
    layer_kernel<false><<<grid, 256, SMEM_TOTAL>>>(h0, l0, 2, 2, h1, l1, nullptr);
    fold_kernel<<<256, 256>>>(W4, b4, g3, be3, 3, 2);
    layer_kernel<true><<<grid, 256, SMEM_TOTAL>>>(h1, l1, 3, -1, nullptr, nullptr, out);
}

// round 11
// speedup vs baseline: 1.5178x; 1.0014x over previous
#include <cuda_runtime.h>
#include <cuda_fp16.h>
#include <math.h>
#include <stdint.h>

constexpr int MT = 32768;
constexpr int D  = 256;

// ---------------- smem layout (bytes) ----------------
constexpr int OFF_BIAS = 0;      // float[128]
constexpr int OFF_SUM  = 512;    // float[128]
constexpr int OFF_SQ   = 1024;   // float[128]
constexpr int OFF_STG  = 2048;
// plane: 128 rows x 64B (k32 fp16), XOR-swizzled 16B segs, no padding
constexpr int PLANE     = 128 * 64;            // 8192
constexpr int T_AHI = 0, T_ALO = PLANE, T_B = 2 * PLANE;
constexpr int STG_BYTES = 3 * PLANE;           // 24576
constexpr int NSTAGE    = 4;
constexpr int SMEM_TOTAL = OFF_STG + NSTAGE * STG_BYTES;   // 100352

// ---------------- device scratch ----------------
__device__ __half g_actHi[2][(size_t)MT * D];
__device__ __half g_actLo[2][(size_t)MT * D];
__device__ __half g_W[4][D * D];     // [n][k] folded fp16 weights (single plane)
__device__ float g_bias[4][D];
__device__ float g_sum[3 * D];
__device__ float g_sq[3 * D];

// ---------------- helpers ----------------
__device__ __forceinline__ uint32_t smem_u32(const void* p) {
    return (uint32_t)__cvta_generic_to_shared(p);
}
__device__ __forceinline__ void cp16(uint32_t sdst, const void* gsrc) {
    asm volatile("cp.async.cg.shared.global [%0], [%1], 16;\n" :: "r"(sdst), "l"(gsrc));
}
#define CP_COMMIT asm volatile("cp.async.commit_group;\n" ::: "memory")

__device__ __forceinline__ float gelu_exact(float x) {
    return 0.5f * x * (1.0f + erff(x * 0.70710678118654752f));
}
__device__ __forceinline__ void split_f16(float x, __half& hi, __half& lo) {
    hi = __float2half(x);
    lo = __float2half(x - __half2float(hi));
}

#define LDSM4(r, addr) \
    asm volatile("ldmatrix.sync.aligned.m8n8.x4.shared.b16 {%0,%1,%2,%3}, [%4];" \
                 : "=r"((r)[0]), "=r"((r)[1]), "=r"((r)[2]), "=r"((r)[3]) : "r"(addr))
#define MMA(acc, a, b0_, b1_) \
    asm volatile("mma.sync.aligned.m16n8k16.row.col.f32.f16.f16.f32 " \
                 "{%0,%1,%2,%3}, {%4,%5,%6,%7}, {%8,%9}, {%0,%1,%2,%3};" \
                 : "+f"((acc)[0]), "+f"((acc)[1]), "+f"((acc)[2]), "+f"((acc)[3]) \
                 : "r"((a)[0]), "r"((a)[1]), "r"((a)[2]), "r"((a)[3]), \
                   "r"(b0_), "r"(b1_))

// ================= prep0: zero stats + gather/split + W1 fold =================
__global__ __launch_bounds__(256)
void prep0_kernel(const int* __restrict__ ids, const float* __restrict__ table,
                  const float* __restrict__ W1, const float* __restrict__ b1) {
    const int tid = threadIdx.x, blk = blockIdx.x;
    if (blk < 256) {
        const int col2 = (tid & 127) * 2;
        const int rsub = tid >> 7;
        uint32_t* dstH = (uint32_t*)g_actHi[0];
        uint32_t* dstL = (uint32_t*)g_actLo[0];
#pragma unroll 4
        for (int i = 0; i < 64; i++) {
            int row = blk * 128 + rsub + i * 2;
            int id  = __ldg(ids + row);
            float2 x = *(const float2*)(table + (size_t)id * D + col2);
            union { __half h[2]; uint32_t u; } ph, pl;
            split_f16(x.x, ph.h[0], pl.h[0]);
            split_f16(x.y, ph.h[1], pl.h[1]);
            size_t o = ((size_t)row * D + col2) >> 1;
            dstH[o] = ph.u; dstL[o] = pl.u;
        }
    } else {
        const int n = blk - 256;
        if (blk == 256) {
            for (int i = tid; i < 3 * D; i += 256) { g_sum[i] = 0.f; g_sq[i] = 0.f; }
        }
        g_W[0][n * D + tid] = __float2half(W1[(size_t)tid * D + n]);
        if (tid == 0) g_bias[0][n] = b1[n];
    }
}

// ================= per-layer fold =================
__global__ __launch_bounds__(256)
void fold_kernel(const float* __restrict__ W, const float* __restrict__ b,
                 const float* __restrict__ gamma, const float* __restrict__ beta,
                 int L, int sl) {
    __shared__ float red[256];
    const int n = blockIdx.x, k = threadIdx.x;
    const float inv_m = 1.0f / (float)MT;
    float mu  = g_sum[sl * D + k] * inv_m;
    float var = g_sq[sl * D + k] * inv_m - mu * mu;
    float a = rsqrtf(var + 1e-5f) * gamma[k];
    float c = beta[k] - mu * a;
    float w = W[(size_t)k * D + n];
    g_W[L][n * D + k] = __float2half(a * w);
    red[k] = c * w;
    __syncthreads();
#pragma unroll
    for (int s = 128; s > 0; s >>= 1) {
        if (k < s) red[k] += red[k + s];
        __syncthreads();
    }
    if (k == 0) g_bias[L][n] = b[n] + red[0];
}

// ================= layer kernel: 128x128 tile, 4-stage k32 pipeline, 2-pass fp16 =================
template <bool FINAL>
__global__ __launch_bounds__(256, 2)
void layer_kernel(const __half* __restrict__ Ahi,
                  const __half* __restrict__ Alo,
                  int wl, int so,
                  __half* __restrict__ Ohi,
                  __half* __restrict__ Olo,
                  float* __restrict__ Ofp)
{
    extern __shared__ char smem[];
    const uint32_t sb = smem_u32(smem);
    const int tid  = threadIdx.x;
    const int lane = tid & 31;
    const int wid  = tid >> 5;
    const int wm   = wid >> 1;
    const int wn   = wid & 1;
    const int n0   = blockIdx.x * 128;
    const int m0   = blockIdx.y * 128;

    const __half* __restrict__ W = g_W[wl];

    // cp.async mapping: thread -> (row = tid>>1, segs {sp, sp+1})
    const int lrow = tid >> 1;
    const int lsp  = (tid & 1) * 2;
    const uint32_t lkey = (uint32_t)((lrow >> 1) & 3);

    auto load_stage = [&](int ch, int s) {
        const uint32_t st = sb + OFF_STG + s * STG_BYTES;
        const int kof = ch * 32;
        const size_t ga = (size_t)(m0 + lrow) * D + kof;
        const size_t gb = (size_t)(n0 + lrow) * D + kof;
        const uint32_t rbase = st + lrow * 64;
#pragma unroll
        for (int i = 0; i < 2; i++) {
            const uint32_t seg = lsp + i;
            const uint32_t d = rbase + ((seg ^ lkey) << 4);
            cp16(d + T_AHI, Ahi + ga + seg * 8);
            cp16(d + T_ALO, Alo + ga + seg * 8);
            cp16(d + T_B,   W   + gb + seg * 8);
        }
    };

    load_stage(0, 0); CP_COMMIT;
    load_stage(1, 1); CP_COMMIT;
    load_stage(2, 2); CP_COMMIT;

    float* sBias = (float*)(smem + OFF_BIAS);
    float* sSum  = (float*)(smem + OFF_SUM);
    float* sSq   = (float*)(smem + OFF_SQ);
    if (tid < 128) {
        sBias[tid] = g_bias[wl][n0 + tid];
        sSum[tid] = 0.f; sSq[tid] = 0.f;
    }

    float acc[2][8][4];
#pragma unroll
    for (int mt = 0; mt < 2; mt++)
#pragma unroll
        for (int n8 = 0; n8 < 8; n8++)
#pragma unroll
            for (int q = 0; q < 4; q++) acc[mt][n8][q] = 0.f;

    // ldmatrix offsets (XOR-swizzled, k16 toggles bit5)
    const int arow = wm * 32 + (lane & 15);
    const uint32_t aOff = (uint32_t)arow * 64
        + ((((uint32_t)(lane >> 4)) ^ (uint32_t)((arow >> 1) & 3)) << 4);
    const int brow = wn * 64 + (lane & 7) + ((lane >> 4) << 3);
    const uint32_t bOff = (uint32_t)brow * 64
        + ((((uint32_t)((lane >> 3) & 1)) ^ (uint32_t)((brow >> 1) & 3)) << 4);

#pragma unroll 1
    for (int ch = 0; ch < 8; ch++) {
        if (ch < 6)      asm volatile("cp.async.wait_group 2;" ::: "memory");
        else if (ch == 6) asm volatile("cp.async.wait_group 1;" ::: "memory");
        else             asm volatile("cp.async.wait_group 0;" ::: "memory");
        __syncthreads();
        if (ch + 3 < 8) { load_stage(ch + 3, (ch + 3) & 3); CP_COMMIT; }

        const uint32_t st = sb + OFF_STG + (ch & 3) * STG_BYTES;
#pragma unroll
        for (int k16 = 0; k16 < 2; k16++) {
            uint32_t bf[4][4];
            uint32_t af[2][4];
            // all B fragments for this k16 (4 LDSM, 16 regs, live across both passes)
#pragma unroll
            for (int nt = 0; nt < 4; nt++)
                LDSM4(bf[nt], (st + T_B + bOff + nt * 1024) ^ (k16 << 5));
            // A-hi fragments
#pragma unroll
            for (int mt = 0; mt < 2; mt++)
                LDSM4(af[mt], (st + T_AHI + aOff + mt * 1024) ^ (k16 << 5));
            // hi pass: 16 MMAs, every accumulator distinct -> 16 independent chains
#pragma unroll
            for (int nt = 0; nt < 4; nt++)
#pragma unroll
                for (int j = 0; j < 2; j++)
#pragma unroll
                    for (int mt = 0; mt < 2; mt++)
                        MMA(acc[mt][nt * 2 + j], af[mt], bf[nt][j * 2], bf[nt][j * 2 + 1]);
            // A-lo fragments (reuse af registers)
#pragma unroll
            for (int mt = 0; mt < 2; mt++)
                LDSM4(af[mt], (st + T_ALO + aOff + mt * 1024) ^ (k16 << 5));
            // lo pass: 16 MMAs, distinct accumulators again
#pragma unroll
            for (int nt = 0; nt < 4; nt++)
#pragma unroll
                for (int j = 0; j < 2; j++)
#pragma unroll
                    for (int mt = 0; mt < 2; mt++)
                        MMA(acc[mt][nt * 2 + j], af[mt], bf[nt][j * 2], bf[nt][j * 2 + 1]);
        }
    }

    // ---------------- epilogue ----------------
    const int r0base = m0 + wm * 32 + (lane >> 2);
#pragma unroll
    for (int n8 = 0; n8 < 8; n8++) {
        const int colL = wn * 64 + n8 * 8 + (lane & 3) * 2;
        const float b0 = sBias[colL], b1 = sBias[colL + 1];
        float s0 = 0.f, s1 = 0.f, q0 = 0.f, q1 = 0.f;
#pragma unroll
        for (int mt = 0; mt < 2; mt++) {
#pragma unroll
            for (int h = 0; h < 2; h++) {
                float v0 = gelu_exact(acc[mt][n8][h * 2 + 0] + b0);
                float v1 = gelu_exact(acc[mt][n8][h * 2 + 1] + b1);
                int row = r0base + mt * 16 + h * 8;
                if (FINAL) {
                    *(float2*)(Ofp + (size_t)row * D + n0 + colL) = make_float2(v0, v1);
                } else {
                    s0 += v0; s1 += v1; q0 += v0 * v0; q1 += v1 * v1;
                    union { __half hh[2]; uint32_t u; } ph, pl;
                    split_f16(v0, ph.hh[0], pl.hh[0]);
                    split_f16(v1, ph.hh[1], pl.hh[1]);
                    size_t o = ((size_t)row * D + n0 + colL) >> 1;
                    ((uint32_t*)Ohi)[o] = ph.u;
                    ((uint32_t*)Olo)[o] = pl.u;
                }
            }
        }
        if (!FINAL) {
#pragma unroll
            for (int off = 4; off < 32; off <<= 1) {
                s0 += __shfl_xor_sync(0xFFFFFFFFu, s0, off);
                s1 += __shfl_xor_sync(0xFFFFFFFFu, s1, off);
                q0 += __shfl_xor_sync(0xFFFFFFFFu, q0, off);
                q1 += __shfl_xor_sync(0xFFFFFFFFu, q1, off);
            }
            if (lane < 4) {
                int c = wn * 64 + n8 * 8 + lane * 2;
                atomicAdd(&sSum[c],     s0);
                atomicAdd(&sSum[c + 1], s1);
                atomicAdd(&sSq[c],      q0);
                atomicAdd(&sSq[c + 1],  q1);
            }
        }
    }

    if (!FINAL) {
        __syncthreads();
        if (tid < 128) {
            atomicAdd(&g_sum[so * D + n0 + tid], sSum[tid]);
            atomicAdd(&g_sq[so * D + n0 + tid],  sSq[tid]);
        }
    }
}

// ================= launch =================
extern "C" void kernel_launch(void* const* d_in, const int* in_sizes, int n_in,
                              void* d_out, int out_size) {
    const int*   ids   = (const int*)d_in[0];
    const float* table = (const float*)d_in[1];
    const float* W1 = (const float*)d_in[2];
    const float* b1 = (const float*)d_in[3];
    const float* W2 = (const float*)d_in[4];
    const float* b2 = (const float*)d_in[5];
    const float* W3 = (const float*)d_in[6];
    const float* b3 = (const float*)d_in[7];
    const float* W4 = (const float*)d_in[8];
    const float* b4 = (const float*)d_in[9];
    const float* g1  = (const float*)d_in[10];
    const float* be1 = (const float*)d_in[11];
    const float* g2  = (const float*)d_in[12];
    const float* be2 = (const float*)d_in[13];
    const float* g3  = (const float*)d_in[14];
    const float* be3 = (const float*)d_in[15];
    float* out = (float*)d_out;

    __half *h0, *l0;
    cudaGetSymbolAddress((void**)&h0, g_actHi);
    cudaGetSymbolAddress((void**)&l0, g_actLo);
    __half* h1 = h0 + (size_t)MT * D;
    __half* l1 = l0 + (size_t)MT * D;

    static bool attr_set = false;
    if (!attr_set) {
        cudaFuncSetAttribute(layer_kernel<false>,
                             cudaFuncAttributeMaxDynamicSharedMemorySize, SMEM_TOTAL);
        cudaFuncSetAttribute(layer_kernel<true>,
                             cudaFuncAttributeMaxDynamicSharedMemorySize, SMEM_TOTAL);
        attr_set = true;
    }

    dim3 grid(2, 256);

    prep0_kernel<<<512, 256>>>(ids, table, W1, b1);

    layer_kernel<false><<<grid, 256, SMEM_TOTAL>>>(h0, l0, 0, 0, h1, l1, nullptr);
    fold_kernel<<<256, 256>>>(W2, b2, g1, be1, 1, 0);
    layer_kernel<false><<<grid, 256, SMEM_TOTAL>>>(h1, l1, 1, 1, h0, l0, nullptr);
    fold_kernel<<<256, 256>>>(W3, b3, g2, be2, 2, 1);
    layer_kernel<false><<<grid, 256, SMEM_TOTAL>>>(h0, l0, 2, 2, h1, l1, nullptr);
    fold_kernel<<<256, 256>>>(W4, b4, g3, be3, 3, 2);
    layer_kernel<true><<<grid, 256, SMEM_TOTAL>>>(h1, l1, 3, -1, nullptr, nullptr, out);
}

// round 14
// speedup vs baseline: 1.5327x; 1.0098x over previous
#include <cuda_runtime.h>
#include <cuda_fp16.h>
#include <math.h>
#include <stdint.h>

constexpr int MT = 32768;
constexpr int D  = 256;
constexpr int NTILES = 512;          // (2 n-halves) x (256 m-tiles)
constexpr int NCTA   = 296;          // 2 per SM on 148 SMs

// ---------------- smem: just the 4-stage ring ----------------
constexpr int PLANE     = 128 * 64;            // 8192 B (128 rows x 64B)
constexpr int T_AHI = 0, T_ALO = PLANE, T_B = 2 * PLANE;
constexpr int STG_BYTES = 3 * PLANE;           // 24576
constexpr int NSTAGE    = 4;
constexpr int SMEM_TOTAL = NSTAGE * STG_BYTES; // 98304

// ---------------- device scratch ----------------
__device__ __half g_actHi[2][(size_t)MT * D];
__device__ __half g_actLo[2][(size_t)MT * D];
__device__ __half g_W[4][D * D];     // [n][k] folded fp16 weights
__device__ float g_bias[4][D];
__device__ float g_sum[3 * D];
__device__ float g_sq[3 * D];

// ---------------- helpers ----------------
__device__ __forceinline__ uint32_t smem_u32(const void* p) {
    return (uint32_t)__cvta_generic_to_shared(p);
}
__device__ __forceinline__ void cp16(uint32_t sdst, const void* gsrc) {
    asm volatile("cp.async.cg.shared.global [%0], [%1], 16;\n" :: "r"(sdst), "l"(gsrc));
}
#define CP_COMMIT asm volatile("cp.async.commit_group;\n" ::: "memory")

__device__ __forceinline__ float gelu_exact(float x) {
    return 0.5f * x * (1.0f + erff(x * 0.70710678118654752f));
}
__device__ __forceinline__ void split_f16(float x, __half& hi, __half& lo) {
    hi = __float2half(x);
    lo = __float2half(x - __half2float(hi));
}

#define LDSM4(r, addr) \
    asm volatile("ldmatrix.sync.aligned.m8n8.x4.shared.b16 {%0,%1,%2,%3}, [%4];" \
                 : "=r"((r)[0]), "=r"((r)[1]), "=r"((r)[2]), "=r"((r)[3]) : "r"(addr))
#define MMA(acc, a, b0_, b1_) \
    asm volatile("mma.sync.aligned.m16n8k16.row.col.f32.f16.f16.f32 " \
                 "{%0,%1,%2,%3}, {%4,%5,%6,%7}, {%8,%9}, {%0,%1,%2,%3};" \
                 : "+f"((acc)[0]), "+f"((acc)[1]), "+f"((acc)[2]), "+f"((acc)[3]) \
                 : "r"((a)[0]), "r"((a)[1]), "r"((a)[2]), "r"((a)[3]), \
                   "r"(b0_), "r"(b1_))

// ================= prep0: zero stats + gather/split + W1 fold =================
__global__ __launch_bounds__(256)
void prep0_kernel(const int* __restrict__ ids, const float* __restrict__ table,
                  const float* __restrict__ W1, const float* __restrict__ b1) {
    const int tid = threadIdx.x, blk = blockIdx.x;
    if (blk < 256) {
        const int col2 = (tid & 127) * 2;
        const int rsub = tid >> 7;
        uint32_t* dstH = (uint32_t*)g_actHi[0];
        uint32_t* dstL = (uint32_t*)g_actLo[0];
#pragma unroll 4
        for (int i = 0; i < 64; i++) {
            int row = blk * 128 + rsub + i * 2;
            int id  = __ldg(ids + row);
            float2 x = *(const float2*)(table + (size_t)id * D + col2);
            union { __half h[2]; uint32_t u; } ph, pl;
            split_f16(x.x, ph.h[0], pl.h[0]);
            split_f16(x.y, ph.h[1], pl.h[1]);
            size_t o = ((size_t)row * D + col2) >> 1;
            dstH[o] = ph.u; dstL[o] = pl.u;
        }
    } else {
        const int n = blk - 256;
        if (blk == 256) {
            for (int i = tid; i < 3 * D; i += 256) { g_sum[i] = 0.f; g_sq[i] = 0.f; }
        }
        g_W[0][n * D + tid] = __float2half(W1[(size_t)tid * D + n]);
        if (tid == 0) g_bias[0][n] = b1[n];
    }
}

// ================= per-layer fold =================
__global__ __launch_bounds__(256)
void fold_kernel(const float* __restrict__ W, const float* __restrict__ b,
                 const float* __restrict__ gamma, const float* __restrict__ beta,
                 int L, int sl) {
    __shared__ float red[256];
    const int n = blockIdx.x, k = threadIdx.x;
    const float inv_m = 1.0f / (float)MT;
    float mu  = g_sum[sl * D + k] * inv_m;
    float var = g_sq[sl * D + k] * inv_m - mu * mu;
    float a = rsqrtf(var + 1e-5f) * gamma[k];
    float c = beta[k] - mu * a;
    float w = W[(size_t)k * D + n];
    g_W[L][n * D + k] = __float2half(a * w);
    red[k] = c * w;
    __syncthreads();
#pragma unroll
    for (int s = 128; s > 0; s >>= 1) {
        if (k < s) red[k] += red[k + s];
        __syncthreads();
    }
    if (k == 0) g_bias[L][n] = b[n] + red[0];
}

// ================= persistent layer kernel =================
// 296 CTAs, each runs 1-2 tiles of 128x128 with one continuous 4-stage ring.
// A group is committed EVERY iteration (empty at the tail) so wait_group 2
// uniformly guarantees chunks 0..gc have landed.
template <bool FINAL>
__global__ __launch_bounds__(256, 2)
void layer_kernel(const __half* __restrict__ Ahi,
                  const __half* __restrict__ Alo,
                  int wl, int so,
                  __half* __restrict__ Ohi,
                  __half* __restrict__ Olo,
                  float* __restrict__ Ofp)
{
    extern __shared__ char smem[];
    const uint32_t sb = smem_u32(smem);
    const int tid  = threadIdx.x;
    const int lane = tid & 31;
    const int wid  = tid >> 5;
    const int wm   = wid >> 1;
    const int wn   = wid & 1;
    const int t0   = blockIdx.x;
    const int ntile = (t0 + NCTA < NTILES) ? 2 : 1;
    const int total = ntile * 8;

    const __half* __restrict__ W = g_W[wl];

    // cp.async mapping: thread -> (row = tid>>1, segs {sp, sp+1})
    const int lrow = tid >> 1;
    const int lsp  = (tid & 1) * 2;
    const uint32_t lkey = (uint32_t)((lrow >> 1) & 3);

    auto load_stage = [&](int gc) {
        const int tidx = t0 + (gc >> 3) * NCTA;
        const int m0l  = (tidx >> 1) * 128;
        const int n0l  = (tidx & 1) * 128;
        const uint32_t st = sb + (gc & 3) * STG_BYTES;
        const int kof = (gc & 7) * 32;
        const size_t ga = (size_t)(m0l + lrow) * D + kof;
        const size_t gb = (size_t)(n0l + lrow) * D + kof;
        const uint32_t rbase = st + lrow * 64;
#pragma unroll
        for (int i = 0; i < 2; i++) {
            const uint32_t seg = lsp + i;
            const uint32_t d = rbase + ((seg ^ lkey) << 4);
            cp16(d + T_AHI, Ahi + ga + seg * 8);
            cp16(d + T_ALO, Alo + ga + seg * 8);
            cp16(d + T_B,   W   + gb + seg * 8);
        }
    };

    load_stage(0); CP_COMMIT;
    load_stage(1); CP_COMMIT;
    load_stage(2); CP_COMMIT;

    float acc[2][8][4];
#pragma unroll
    for (int mt = 0; mt < 2; mt++)
#pragma unroll
        for (int n8 = 0; n8 < 8; n8++)
#pragma unroll
            for (int q = 0; q < 4; q++) acc[mt][n8][q] = 0.f;

    // ldmatrix offsets (XOR-swizzled, k16 toggles bit5)
    const int arow = wm * 32 + (lane & 15);
    const uint32_t aOff = (uint32_t)arow * 64
        + ((((uint32_t)(lane >> 4)) ^ (uint32_t)((arow >> 1) & 3)) << 4);
    const int brow = wn * 64 + (lane & 7) + ((lane >> 4) << 3);
    const uint32_t bOff = (uint32_t)brow * 64
        + ((((uint32_t)((lane >> 3) & 1)) ^ (uint32_t)((brow >> 1) & 3)) << 4);

#pragma unroll 1
    for (int gc = 0; gc < total; gc++) {
        asm volatile("cp.async.wait_group 2;" ::: "memory");
        __syncthreads();
        // ALWAYS commit a group (possibly empty) so the wait arithmetic is uniform.
        if (gc + 3 < total) load_stage(gc + 3);
        CP_COMMIT;

        const uint32_t st = sb + (gc & 3) * STG_BYTES;
#pragma unroll
        for (int k16 = 0; k16 < 2; k16++) {
            uint32_t bf[4][4];
            uint32_t af[2][4];
#pragma unroll
            for (int nt = 0; nt < 4; nt++)
                LDSM4(bf[nt], (st + T_B + bOff + nt * 1024) ^ (k16 << 5));
#pragma unroll
            for (int mt = 0; mt < 2; mt++)
                LDSM4(af[mt], (st + T_AHI + aOff + mt * 1024) ^ (k16 << 5));
#pragma unroll
            for (int nt = 0; nt < 4; nt++)
#pragma unroll
                for (int j = 0; j < 2; j++)
#pragma unroll
                    for (int mt = 0; mt < 2; mt++)
                        MMA(acc[mt][nt * 2 + j], af[mt], bf[nt][j * 2], bf[nt][j * 2 + 1]);
#pragma unroll
            for (int mt = 0; mt < 2; mt++)
                LDSM4(af[mt], (st + T_ALO + aOff + mt * 1024) ^ (k16 << 5));
#pragma unroll
            for (int nt = 0; nt < 4; nt++)
#pragma unroll
                for (int j = 0; j < 2; j++)
#pragma unroll
                    for (int mt = 0; mt < 2; mt++)
                        MMA(acc[mt][nt * 2 + j], af[mt], bf[nt][j * 2], bf[nt][j * 2 + 1]);
        }

        if ((gc & 7) == 7) {
            // -------- epilogue for the tile just finished --------
            // (next tile's first 3 chunks are already in flight)
            const int tidx = t0 + (gc >> 3) * NCTA;
            const int m0   = (tidx >> 1) * 128;
            const int n0   = (tidx & 1) * 128;
            const int r0base = m0 + wm * 32 + (lane >> 2);
            const float2* bp = (const float2*)(g_bias[wl] + n0);
#pragma unroll
            for (int n8 = 0; n8 < 8; n8++) {
                const int colL = wn * 64 + n8 * 8 + (lane & 3) * 2;
                const float2 bb = __ldg(bp + (colL >> 1));
                const float b0 = bb.x, b1 = bb.y;
                float s0 = 0.f, s1 = 0.f, q0 = 0.f, q1 = 0.f;
#pragma unroll
                for (int mt = 0; mt < 2; mt++) {
#pragma unroll
                    for (int h = 0; h < 2; h++) {
                        float v0 = gelu_exact(acc[mt][n8][h * 2 + 0] + b0);
                        float v1 = gelu_exact(acc[mt][n8][h * 2 + 1] + b1);
                        int row = r0base + mt * 16 + h * 8;
                        if (FINAL) {
                            *(float2*)(Ofp + (size_t)row * D + n0 + colL) = make_float2(v0, v1);
                        } else {
                            s0 += v0; s1 += v1; q0 += v0 * v0; q1 += v1 * v1;
                            union { __half hh[2]; uint32_t u; } ph, pl;
                            split_f16(v0, ph.hh[0], pl.hh[0]);
                            split_f16(v1, ph.hh[1], pl.hh[1]);
                            size_t o = ((size_t)row * D + n0 + colL) >> 1;
                            ((uint32_t*)Ohi)[o] = ph.u;
                            ((uint32_t*)Olo)[o] = pl.u;
                        }
                    }
                }
                if (!FINAL) {
#pragma unroll
                    for (int off = 4; off < 32; off <<= 1) {
                        s0 += __shfl_xor_sync(0xFFFFFFFFu, s0, off);
                        s1 += __shfl_xor_sync(0xFFFFFFFFu, s1, off);
                        q0 += __shfl_xor_sync(0xFFFFFFFFu, q0, off);
                        q1 += __shfl_xor_sync(0xFFFFFFFFu, q1, off);
                    }
                    if (lane < 4) {
                        int c = so * D + n0 + wn * 64 + n8 * 8 + lane * 2;
                        atomicAdd(&g_sum[c],     s0);
                        atomicAdd(&g_sum[c + 1], s1);
                        atomicAdd(&g_sq[c],      q0);
                        atomicAdd(&g_sq[c + 1],  q1);
                    }
                }
            }
            if (gc + 1 < total) {
#pragma unroll
                for (int mt = 0; mt < 2; mt++)
#pragma unroll
                    for (int n8 = 0; n8 < 8; n8++)
#pragma unroll
                        for (int q = 0; q < 4; q++) acc[mt][n8][q] = 0.f;
            }
        }
    }
}

// ================= launch =================
extern "C" void kernel_launch(void* const* d_in, const int* in_sizes, int n_in,
                              void* d_out, int out_size) {
    const int*   ids   = (const int*)d_in[0];
    const float* table = (const float*)d_in[1];
    const float* W1 = (const float*)d_in[2];
    const float* b1 = (const float*)d_in[3];
    const float* W2 = (const float*)d_in[4];
    const float* b2 = (const float*)d_in[5];
    const float* W3 = (const float*)d_in[6];
    const float* b3 = (const float*)d_in[7];
    const float* W4 = (const float*)d_in[8];
    const float* b4 = (const float*)d_in[9];
    const float* g1  = (const float*)d_in[10];
    const float* be1 = (const float*)d_in[11];
    const float* g2  = (const float*)d_in[12];
    const float* be2 = (const float*)d_in[13];
    const float* g3  = (const float*)d_in[14];
    const float* be3 = (const float*)d_in[15];
    float* out = (float*)d_out;

    __half *h0, *l0;
    cudaGetSymbolAddress((void**)&h0, g_actHi);
    cudaGetSymbolAddress((void**)&l0, g_actLo);
    __half* h1 = h0 + (size_t)MT * D;
    __half* l1 = l0 + (size_t)MT * D;

    static bool attr_set = false;
    if (!attr_set) {
        cudaFuncSetAttribute(layer_kernel<false>,
                             cudaFuncAttributeMaxDynamicSharedMemorySize, SMEM_TOTAL);
        cudaFuncSetAttribute(layer_kernel<true>,
                             cudaFuncAttributeMaxDynamicSharedMemorySize, SMEM_TOTAL);
        attr_set = true;
    }

    prep0_kernel<<<512, 256>>>(ids, table, W1, b1);

    layer_kernel<false><<<NCTA, 256, SMEM_TOTAL>>>(h0, l0, 0, 0, h1, l1, nullptr);
    fold_kernel<<<256, 256>>>(W2, b2, g1, be1, 1, 0);
    layer_kernel<false><<<NCTA, 256, SMEM_TOTAL>>>(h1, l1, 1, 1, h0, l0, nullptr);
    fold_kernel<<<256, 256>>>(W3, b3, g2, be2, 2, 1);
    layer_kernel<false><<<NCTA, 256, SMEM_TOTAL>>>(h0, l0, 2, 2, h1, l1, nullptr);
    fold_kernel<<<256, 256>>>(W4, b4, g3, be3, 3, 2);
    layer_kernel<true><<<NCTA, 256, SMEM_TOTAL>>>(h1, l1, 3, -1, nullptr, nullptr, out);
}